// round 1
// baseline (speedup 1.0000x reference)
#include <cuda_runtime.h>
#include <cuda_bf16.h>
#include <cub/cub.cuh>
#include <cstdint>

// Problem constants (fixed by reference setup_inputs)
#define E_E 500000      // raw edges
#define E_A 1000000     // arrwp edges
#define E_T 1500000     // total
#define N_NODES 50000u
#define EMB 64
#define IND 32

// ---------------- static device scratch (no allocations allowed) -------------
__device__ unsigned      g_keys[E_T];
__device__ unsigned      g_keysAlt[E_T];
__device__ unsigned      g_vals[E_T];
__device__ unsigned      g_valsAlt[E_T];
__device__ int           g_flags[E_T];
__device__ int           g_seg[E_T];
#define TEMP_BYTES (64u * 1024u * 1024u)
__device__ unsigned char g_cubTemp[TEMP_BYTES];

// ---------------- kernels ----------------------------------------------------

// Build 32-bit sort keys (row*50000+col) and payload = original edge id.
__global__ void k_build(const int* __restrict__ eidx, const int* __restrict__ aidx,
                        unsigned* __restrict__ keys, unsigned* __restrict__ vals) {
    int i = blockIdx.x * blockDim.x + threadIdx.x;
    if (i >= E_T) return;
    int r, c;
    if (i < E_E) { r = eidx[i];        c = eidx[E_E + i]; }
    else         { int j = i - E_E; r = aidx[j]; c = aidx[E_A + j]; }
    keys[i] = (unsigned)r * N_NODES + (unsigned)c;
    vals[i] = (unsigned)i;
}

// Segment-head flags on the sorted keys.
__global__ void k_flags(const unsigned* __restrict__ keys, int* __restrict__ flags) {
    int i = blockIdx.x * blockDim.x + threadIdx.x;
    if (i >= E_T) return;
    flags[i] = (i == 0) || (keys[i] != keys[i - 1]);
}

// Warp-per-sorted-position gather. Persistent grid-stride so each warp loads
// its two W rows (64 floats) into registers exactly once.
// Output layout (float32): [uniq_r(E_T) | uniq_c(E_T) | attr_sum(E_T*64) | num_unique]
__global__ __launch_bounds__(256)
void k_gather(const unsigned* __restrict__ keys, const unsigned* __restrict__ vals,
              const int* __restrict__ seg,
              const float* __restrict__ edge_attr, const float* __restrict__ arrwp_attr,
              const float* __restrict__ W, float* __restrict__ out) {
    const int  lane = threadIdx.x & 31;
    const int  wpb  = blockDim.x >> 5;
    long       warpId = (long)blockIdx.x * wpb + (threadIdx.x >> 5);
    const long nWarps = (long)gridDim.x * wpb;

    // W rows `lane` and `lane+32` in registers (W is [64,32] row-major).
    float w0[IND], w1[IND];
#pragma unroll
    for (int k = 0; k < IND; k++) {
        w0[k] = __ldg(&W[lane * IND + k]);
        w1[k] = __ldg(&W[(lane + 32) * IND + k]);
    }

    float* __restrict__ outR = out;
    float* __restrict__ outC = out + E_T;
    float* __restrict__ outA = out + 2L * E_T;

    for (long i = warpId; i < E_T; i += nWarps) {
        unsigned k0 = keys[i];
        if (i > 0 && keys[i - 1] == k0) continue;   // not a segment head
        int s = seg[i] - 1;                          // rank in sorted-unique order

        float acc0 = 0.f, acc1 = 0.f;
        long j = i;
        do {
            unsigned e = vals[j];
            if (e < E_E) {
                const float* row = edge_attr + (long)e * EMB;
                acc0 += row[lane];
                acc1 += row[lane + 32];
            } else {
                const float4* a4 = (const float4*)(arrwp_attr + (long)(e - E_E) * IND);
#pragma unroll
                for (int kk = 0; kk < 8; kk++) {
                    float4 av = __ldg(&a4[kk]);   // uniform across warp -> L1 broadcast
                    acc0 += av.x * w0[4*kk]   + av.y * w0[4*kk+1]
                          + av.z * w0[4*kk+2] + av.w * w0[4*kk+3];
                    acc1 += av.x * w1[4*kk]   + av.y * w1[4*kk+1]
                          + av.z * w1[4*kk+2] + av.w * w1[4*kk+3];
                }
            }
            j++;
        } while (j < E_T && keys[j] == k0);

        if (lane == 0) {
            outR[s] = (float)(k0 / N_NODES);
            outC[s] = (float)(k0 % N_NODES);
        }
        outA[(long)s * EMB + lane]      = acc0;
        outA[(long)s * EMB + 32 + lane] = acc1;
    }
}

// Fill the padded tail: uniq_r/uniq_c = -1, attr_sum = 0 for s >= num_unique,
// and write num_unique as the final element. Work is proportional to actual tail.
__global__ void k_tail(const int* __restrict__ seg, float* __restrict__ out) {
    const int  nu     = seg[E_T - 1];
    const long tid    = (long)blockIdx.x * blockDim.x + threadIdx.x;
    const long stride = (long)gridDim.x * blockDim.x;

    for (long s = nu + tid; s < E_T; s += stride) {
        out[s]        = -1.0f;
        out[E_T + s]  = -1.0f;
    }
    float* outA = out + 2L * E_T;
    for (long t = (long)nu * EMB + tid; t < (long)E_T * EMB; t += stride)
        outA[t] = 0.0f;
    if (tid == 0)
        out[2L * E_T + (long)E_T * EMB] = (float)nu;
}

// ---------------- launch ------------------------------------------------------
extern "C" void kernel_launch(void* const* d_in, const int* in_sizes, int n_in,
                              void* d_out, int out_size) {
    const int*   eidx  = (const int*)d_in[0];
    const float* eattr = (const float*)d_in[1];
    const int*   aidx  = (const int*)d_in[2];
    const float* aattr = (const float*)d_in[3];
    const float* W     = (const float*)d_in[4];
    float*       out   = (float*)d_out;

    unsigned *keys, *keysAlt, *vals, *valsAlt;
    int *flags, *seg;
    void* temp;
    cudaGetSymbolAddress((void**)&keys,    g_keys);
    cudaGetSymbolAddress((void**)&keysAlt, g_keysAlt);
    cudaGetSymbolAddress((void**)&vals,    g_vals);
    cudaGetSymbolAddress((void**)&valsAlt, g_valsAlt);
    cudaGetSymbolAddress((void**)&flags,   g_flags);
    cudaGetSymbolAddress((void**)&seg,     g_seg);
    cudaGetSymbolAddress(&temp,            g_cubTemp);

    const int TB = 256;

    // 1. Build keys/payloads
    k_build<<<(E_T + TB - 1) / TB, TB>>>(eidx, aidx, keys, vals);

    // 2. Radix sort 32-bit keys + payload (CUB, preallocated temp, capturable)
    size_t tb = TEMP_BYTES;
    cub::DeviceRadixSort::SortPairs(temp, tb, keys, keysAlt, vals, valsAlt,
                                    E_T, 0, 32, (cudaStream_t)0);

    // 3. Head flags + inclusive scan -> segment ranks
    k_flags<<<(E_T + TB - 1) / TB, TB>>>(keysAlt, flags);
    tb = TEMP_BYTES;
    cub::DeviceScan::InclusiveSum(temp, tb, flags, seg, E_T, (cudaStream_t)0);

    // 4. Gather/sum per unique (row,col); fused on-the-fly projection for arrwp edges
    k_gather<<<2368, TB>>>(keysAlt, valsAlt, seg, eattr, aattr, W, out);

    // 5. Pad tail + write num_unique
    k_tail<<<512, TB>>>(seg, out);
}

// round 3
// speedup vs baseline: 1.2246x; 1.2246x over previous
#include <cuda_runtime.h>
#include <cuda_bf16.h>
#include <cub/cub.cuh>
#include <cstdint>

// Problem constants (fixed by reference setup_inputs)
#define E_E 500000      // raw edges
#define E_A 1000000     // arrwp edges
#define E_T 1500000     // total
#define N_NODES 50000u
#define EMB 64
#define IND 32

// ---------------- static device scratch (no allocations allowed) -------------
__device__ unsigned      g_keys[E_T];
__device__ unsigned      g_keysAlt[E_T];
__device__ unsigned      g_vals[E_T];
__device__ unsigned      g_valsAlt[E_T];
__device__ int           g_flags[E_T];
__device__ int           g_seg[E_T];
__device__ float         g_proj[(size_t)E_A * EMB];   // 256 MB projection scratch
#define TEMP_BYTES (64u * 1024u * 1024u)
__device__ unsigned char g_cubTemp[TEMP_BYTES];

// ---------------- packed f32x2 helpers (sm_10x FFMA2) ------------------------
__device__ __forceinline__ unsigned long long pk2(float x, float y) {
    unsigned long long r;
    asm("mov.b64 %0, {%1, %2};" : "=l"(r) : "f"(x), "f"(y));
    return r;
}
__device__ __forceinline__ void upk2(unsigned long long v, float& x, float& y) {
    asm("mov.b64 {%0, %1}, %2;" : "=f"(x), "=f"(y) : "l"(v));
}
__device__ __forceinline__ unsigned long long ffma2(unsigned long long a,
                                                    unsigned long long b,
                                                    unsigned long long c) {
    unsigned long long d;
    asm("fma.rn.f32x2 %0, %1, %2, %3;" : "=l"(d) : "l"(a), "l"(b), "l"(c));
    return d;
}

// ---------------- kernels ----------------------------------------------------

// Build 32-bit sort keys (row*50000+col) and payload = original edge id.
__global__ void k_build(const int* __restrict__ eidx, const int* __restrict__ aidx,
                        unsigned* __restrict__ keys, unsigned* __restrict__ vals) {
    int i = blockIdx.x * blockDim.x + threadIdx.x;
    if (i >= E_T) return;
    int r, c;
    if (i < E_E) { r = eidx[i];        c = eidx[E_E + i]; }
    else         { int j = i - E_E; r = aidx[j]; c = aidx[E_A + j]; }
    keys[i] = (unsigned)r * N_NODES + (unsigned)c;
    vals[i] = (unsigned)i;
}

// Segment-head flags on the sorted keys.
__global__ void k_flags(const unsigned* __restrict__ keys, int* __restrict__ flags) {
    int i = blockIdx.x * blockDim.x + threadIdx.x;
    if (i >= E_T) return;
    flags[i] = (i == 0) || (keys[i] != keys[i - 1]);
}

// Dense streaming projection: proj[e] = arrwp_attr[e] @ W^T for all 1M edges.
// Warp per edge (grid-stride). Each lane owns output cols (lane, lane+32);
// the 64 W values it needs are held as 32 packed f32x2 registers, and the
// inner product uses packed FFMA2 (2 MACs/inst). arrwp row is read as 8
// warp-uniform float4 loads (L1 broadcast).
__global__ __launch_bounds__(256)
void k_proj(const float* __restrict__ arrwp, const float* __restrict__ W,
            float* __restrict__ proj) {
    const int lane   = threadIdx.x & 31;
    const int wpb    = blockDim.x >> 5;
    int       warpId = blockIdx.x * wpb + (threadIdx.x >> 5);
    const int nWarps = gridDim.x * wpb;

    // pw[k] = (W[lane][k], W[lane+32][k]); W is [64,32] row-major.
    unsigned long long pw[IND];
#pragma unroll
    for (int k = 0; k < IND; k++)
        pw[k] = pk2(__ldg(&W[lane * IND + k]), __ldg(&W[(lane + 32) * IND + k]));

    for (int e = warpId; e < E_A; e += nWarps) {
        const float4* a4 = (const float4*)(arrwp + (size_t)e * IND);
        unsigned long long acc0 = 0ull, acc1 = 0ull;   // two chains for ILP
#pragma unroll
        for (int kk = 0; kk < 8; kk++) {
            float4 av = __ldg(&a4[kk]);
            acc0 = ffma2(pk2(av.x, av.x), pw[4 * kk + 0], acc0);
            acc1 = ffma2(pk2(av.y, av.y), pw[4 * kk + 1], acc1);
            acc0 = ffma2(pk2(av.z, av.z), pw[4 * kk + 2], acc0);
            acc1 = ffma2(pk2(av.w, av.w), pw[4 * kk + 3], acc1);
        }
        float a0x, a0y, a1x, a1y;
        upk2(acc0, a0x, a0y);
        upk2(acc1, a1x, a1y);
        proj[(size_t)e * EMB + lane]      = a0x + a1x;
        proj[(size_t)e * EMB + 32 + lane] = a0y + a1y;
    }
}

// Pure data-movement gather: warp per sorted position. Singletons (99.97%)
// are straight copies; rare multi-element segments are summed serially by the
// head warp in sorted (stable) order — deterministic and reference-matching.
// Output layout (float32): [uniq_r(E_T) | uniq_c(E_T) | attr_sum(E_T*64) | num_unique]
__global__ __launch_bounds__(256)
void k_copy(const unsigned* __restrict__ keys, const unsigned* __restrict__ vals,
            const int* __restrict__ seg,
            const float* __restrict__ edge_attr, const float* __restrict__ proj,
            float* __restrict__ out) {
    const int  lane = threadIdx.x & 31;
    const long i    = (long)blockIdx.x * (blockDim.x >> 5) + (threadIdx.x >> 5);
    if (i >= E_T) return;

    unsigned k0 = keys[i];
    if (i > 0 && keys[i - 1] == k0) return;       // not a segment head
    const int s = seg[i] - 1;

    unsigned e = vals[i];
    const float* src = (e < E_E) ? edge_attr + (size_t)e * EMB
                                 : proj + (size_t)(e - E_E) * EMB;
    float v0 = src[lane];
    float v1 = src[lane + 32];

    // Rare duplicate tail (expected ~450 total across the whole launch).
    long j = i + 1;
    while (j < E_T && keys[j] == k0) {
        unsigned e2 = vals[j];
        const float* s2 = (e2 < E_E) ? edge_attr + (size_t)e2 * EMB
                                     : proj + (size_t)(e2 - E_E) * EMB;
        v0 += s2[lane];
        v1 += s2[lane + 32];
        j++;
    }

    if (lane == 0) {
        out[s]       = (float)(k0 / N_NODES);
        out[E_T + s] = (float)(k0 % N_NODES);
    }
    float* outA = out + 2L * E_T;
    outA[(size_t)s * EMB + lane]      = v0;
    outA[(size_t)s * EMB + 32 + lane] = v1;
}

// Fill the padded tail: uniq_r/uniq_c = -1, attr_sum = 0 for s >= num_unique,
// and write num_unique as the final element.
__global__ void k_tail(const int* __restrict__ seg, float* __restrict__ out) {
    const int  nu     = seg[E_T - 1];
    const long tid    = (long)blockIdx.x * blockDim.x + threadIdx.x;
    const long stride = (long)gridDim.x * blockDim.x;

    for (long s = nu + tid; s < E_T; s += stride) {
        out[s]       = -1.0f;
        out[E_T + s] = -1.0f;
    }
    float* outA = out + 2L * E_T;
    for (long t = (long)nu * EMB + tid; t < (long)E_T * EMB; t += stride)
        outA[t] = 0.0f;
    if (tid == 0)
        out[2L * E_T + (long)E_T * EMB] = (float)nu;
}

// ---------------- launch ------------------------------------------------------
extern "C" void kernel_launch(void* const* d_in, const int* in_sizes, int n_in,
                              void* d_out, int out_size) {
    const int*   eidx  = (const int*)d_in[0];
    const float* eattr = (const float*)d_in[1];
    const int*   aidx  = (const int*)d_in[2];
    const float* aattr = (const float*)d_in[3];
    const float* W     = (const float*)d_in[4];
    float*       out   = (float*)d_out;

    unsigned *keys, *keysAlt, *vals, *valsAlt;
    int *flags, *seg;
    float* proj;
    void* temp;
    cudaGetSymbolAddress((void**)&keys,    g_keys);
    cudaGetSymbolAddress((void**)&keysAlt, g_keysAlt);
    cudaGetSymbolAddress((void**)&vals,    g_vals);
    cudaGetSymbolAddress((void**)&valsAlt, g_valsAlt);
    cudaGetSymbolAddress((void**)&flags,   g_flags);
    cudaGetSymbolAddress((void**)&seg,     g_seg);
    cudaGetSymbolAddress((void**)&proj,    g_proj);
    cudaGetSymbolAddress(&temp,            g_cubTemp);

    const int TB = 256;

    // 1. Build keys/payloads
    k_build<<<(E_T + TB - 1) / TB, TB>>>(eidx, aidx, keys, vals);

    // 2. Dense projection (independent of sort result; streaming + FFMA2)
    k_proj<<<2368, TB>>>(aattr, W, proj);

    // 3. Radix sort 32-bit keys + payload (CUB, preallocated temp, capturable)
    size_t tb = TEMP_BYTES;
    cub::DeviceRadixSort::SortPairs(temp, tb, keys, keysAlt, vals, valsAlt,
                                    E_T, 0, 32, (cudaStream_t)0);

    // 4. Head flags + inclusive scan -> segment ranks
    k_flags<<<(E_T + TB - 1) / TB, TB>>>(keysAlt, flags);
    tb = TEMP_BYTES;
    cub::DeviceScan::InclusiveSum(temp, tb, flags, seg, E_T, (cudaStream_t)0);

    // 5. Gather/copy per unique (row,col)
    k_copy<<<(E_T + 7) / 8, TB>>>(keysAlt, valsAlt, seg, eattr, proj, out);

    // 6. Pad tail + write num_unique
    k_tail<<<512, TB>>>(seg, out);
}